// round 5
// baseline (speedup 1.0000x reference)
#include <cuda_runtime.h>
#include <cuda_fp16.h>
#include <stdint.h>

// Problem constants
constexpr int BB = 128;    // batch
constexpr int TT = 512;    // seq len
constexpr int EE = 256;    // embed
constexpr int HH = 512;    // hidden
constexpr int GG = 2048;   // 4*H gates
constexpr int MR = BB * TT;  // 65536 rows

constexpr int NGROUP = 8;   // batch groups (clusters)
constexpr int NSLICE = 16;  // CTAs per cluster
constexpr int BSUB   = 16;  // batch rows per group

// ---------------- static device scratch (allocation-free) ----------------
__device__ __half g_x16[(size_t)MR * EE];
__device__ __half g_h1 [(size_t)MR * HH];
__device__ __half g_xg [(size_t)MR * GG];     // 256 MB fp16, reused across layers
__device__ __half g_wih0p[GG * EE];
__device__ __half g_wih1p[GG * HH];
__device__ __half g_whh0p[GG * HH];
__device__ __half g_whh1p[GG * HH];
__device__ float  g_bias0[GG];
__device__ float  g_bias1[GG];
__device__ float  g_hlast[BB * HH];

// Column permutation: new index m -> original gate column n
// m = c*128 + u*4 + q  (c = CTA slice 0..15, u = hidden-in-slice 0..31, q = gate 0..3)
// n = q*512 + c*32 + u   (gates interleaved per hidden unit -> uint2 xg loads)
__device__ __forceinline__ int perm_orig(int m) {
    int cc = m >> 7, l = m & 127, u = l >> 2, q = l & 3;
    return q * 512 + cc * 32 + u;
}

// ---------------- prep kernels ----------------
__global__ void k_conv_x(const float* __restrict__ x) {
    size_t i = (size_t)blockIdx.x * blockDim.x + threadIdx.x;
    if (i < (size_t)MR * EE) g_x16[i] = __float2half(x[i]);
}

__global__ void k_prep_w(const float* __restrict__ wih0, const float* __restrict__ whh0,
                         const float* __restrict__ wih1, const float* __restrict__ whh1) {
    int which = blockIdx.y;
    size_t i = (size_t)blockIdx.x * blockDim.x + threadIdx.x;
    const float* src; __half* dst; int K;
    if      (which == 0) { src = wih0; dst = g_wih0p; K = EE; }
    else if (which == 1) { src = whh0; dst = g_whh0p; K = HH; }
    else if (which == 2) { src = wih1; dst = g_wih1p; K = HH; }
    else                 { src = whh1; dst = g_whh1p; K = HH; }
    if (i >= (size_t)GG * K) return;
    int m = (int)(i / K), k = (int)(i % K);
    int n = perm_orig(m);
    dst[i] = __float2half(src[(size_t)n * K + k]);
}

__global__ void k_prep_b(const float* __restrict__ bih0, const float* __restrict__ bhh0,
                         const float* __restrict__ bih1, const float* __restrict__ bhh1) {
    int m = blockIdx.x * blockDim.x + threadIdx.x;
    if (m >= GG) return;
    int n = perm_orig(m);
    if (blockIdx.y == 0) g_bias0[m] = bih0[n] + bhh0[n];
    else                 g_bias1[m] = bih1[n] + bhh1[n];
}

// ---------------- asm helpers ----------------
__device__ __forceinline__ void mma16816(float* d, const uint32_t* a, uint32_t b0, uint32_t b1) {
    asm volatile(
        "mma.sync.aligned.m16n8k16.row.col.f32.f16.f16.f32 "
        "{%0,%1,%2,%3},{%4,%5,%6,%7},{%8,%9},{%0,%1,%2,%3};"
        : "+f"(d[0]), "+f"(d[1]), "+f"(d[2]), "+f"(d[3])
        : "r"(a[0]), "r"(a[1]), "r"(a[2]), "r"(a[3]), "r"(b0), "r"(b1));
}

__device__ __forceinline__ void ldsm4(uint32_t& r0, uint32_t& r1, uint32_t& r2, uint32_t& r3,
                                      uint32_t addr) {
    asm volatile("ldmatrix.sync.aligned.m8n8.x4.shared.b16 {%0,%1,%2,%3}, [%4];"
                 : "=r"(r0), "=r"(r1), "=r"(r2), "=r"(r3) : "r"(addr));
}

__device__ __forceinline__ void cp16(uint32_t dst, const void* src) {
    asm volatile("cp.async.cg.shared.global [%0], [%1], 16;" :: "r"(dst), "l"(src));
}
__device__ __forceinline__ void cp_commit() { asm volatile("cp.async.commit_group;"); }

__device__ __forceinline__ float tanhfast(float x) {
    float y;
    asm("tanh.approx.f32 %0, %1;" : "=f"(y) : "f"(x));
    return y;
}
__device__ __forceinline__ float sigm(float x) {
    return fmaf(0.5f, tanhfast(0.5f * x), 0.5f);
}

// ---------------- xg GEMM: C[M, 2048] = A[M,K] @ Wp^T + bias (fp16 out) ----------------
// BM=128, BN=64, BK=32, 256 threads (8 warps: 4 M x 2 N, warp tile 32x32)
// 3-stage cp.async ring (wait_group 1), ldmatrix fragments, 2 CTAs/SM.
constexpr int GEMM_STAGE = (128 + 64) * 40;            // halves per stage
constexpr int GEMM_SMEM  = 3 * GEMM_STAGE * 2;         // 46080 B

template <int K>
__global__ __launch_bounds__(256, 2) void k_gemm_xg(int layer) {
    const __half* __restrict__ A = layer ? g_h1    : g_x16;
    const __half* __restrict__ W = layer ? g_wih1p : g_wih0p;
    const float*  __restrict__ bias = layer ? g_bias1 : g_bias0;

    extern __shared__ __align__(16) __half gsm[];

    int tid = threadIdx.x;
    int m0 = blockIdx.y * 128;
    int n0 = blockIdx.x * 64;
    int lane = tid & 31, warp = tid >> 5;
    int wm = warp & 3, wn = warp >> 2;
    int r = lane >> 2, tg = lane & 3;

    uint32_t gsmu = (uint32_t)__cvta_generic_to_shared(gsm);
    const uint32_t stageB = GEMM_STAGE * 2;

    // cp.async indices: A 128x32 (2 uint4-chunks/thread), B 64x32 (1 chunk/thread)
    int ar0 = tid >> 2, ac4 = tid & 3;
    int br0 = tid >> 2, bc4 = tid & 3;

    // ldmatrix lane offsets (bytes), row stride 40 halves = 80 B
    uint32_t laneA = (uint32_t)(((lane & 15) * 40 + ((lane >> 4) << 3)) << 1);
    int bnn = wn * 32 + ((lane >> 4) & 1) * 8 + (lane & 7);
    uint32_t laneB = (uint32_t)((bnn * 40 + ((lane >> 3) & 1) * 8) << 1);

    float acc[2][4][4] = {};
    constexpr int KT = K / 32;

    auto load_stage = [&](int st, int kt) {
        uint32_t base = gsmu + st * stageB;
#pragma unroll
        for (int i = 0; i < 2; i++) {
            int row = ar0 + i * 64;
            cp16(base + (uint32_t)((row * 5 + ac4) * 16),
                 A + (size_t)(m0 + row) * K + kt * 32 + ac4 * 8);
        }
        cp16(base + (uint32_t)(128 * 80) + (uint32_t)((br0 * 5 + bc4) * 16),
             W + (size_t)(n0 + br0) * K + kt * 32 + bc4 * 8);
        cp_commit();
    };

    load_stage(0, 0);
    if (KT > 1) load_stage(1, 1);

    int st = 0;
    for (int kt = 0; kt < KT; kt++) {
        asm volatile("cp.async.wait_group 1;");
        __syncthreads();
        if (kt + 2 < KT) {
            int ns = st + 2; if (ns >= 3) ns -= 3;
            load_stage(ns, kt + 2);
        }
        uint32_t abase = gsmu + st * stageB;
        uint32_t bbase = abase + (uint32_t)(128 * 80);
#pragma unroll
        for (int kk = 0; kk < 2; kk++) {
            uint32_t kko = (uint32_t)(kk * 32);
            uint32_t a[2][4];
#pragma unroll
            for (int mt = 0; mt < 2; mt++) {
                uint32_t addr = abase + (uint32_t)(((wm * 32 + mt * 16) * 40) << 1) + laneA + kko;
                ldsm4(a[mt][0], a[mt][1], a[mt][2], a[mt][3], addr);
            }
            uint32_t p0, p1, p2, p3, q0, q1, q2, q3;
            ldsm4(p0, p1, p2, p3, bbase + laneB + kko);
            ldsm4(q0, q1, q2, q3, bbase + laneB + (uint32_t)((16 * 40) << 1) + kko);
#pragma unroll
            for (int mt = 0; mt < 2; mt++) {
                mma16816(acc[mt][0], a[mt], p0, p1);
                mma16816(acc[mt][1], a[mt], p2, p3);
                mma16816(acc[mt][2], a[mt], q0, q1);
                mma16816(acc[mt][3], a[mt], q2, q3);
            }
        }
        if (++st == 3) st = 0;
    }

    // epilogue: add bias, store fp16
#pragma unroll
    for (int mt = 0; mt < 2; mt++)
#pragma unroll
        for (int nt = 0; nt < 4; nt++) {
            int m = m0 + wm * 32 + mt * 16 + r;
            int n = n0 + wn * 32 + nt * 8 + tg * 2;
            float b0 = bias[n], b1 = bias[n + 1];
            __half2 v0 = __floats2half2_rn(acc[mt][nt][0] + b0, acc[mt][nt][1] + b1);
            __half2 v1 = __floats2half2_rn(acc[mt][nt][2] + b0, acc[mt][nt][3] + b1);
            *(__half2*)&g_xg[(size_t)m * GG + n] = v0;
            *(__half2*)&g_xg[(size_t)(m + 8) * GG + n] = v1;
        }
}

// ---------------- persistent LSTM recurrence (16-CTA clusters, DSMEM h exchange) --------
// 128 CTAs = 8 clusters x 16 slices, 256 threads each (8 warps, 16 gate cols/warp).
// CTA (g,c): batch rows [g*16, g*16+16), hidden [c*32, c*32+32),
// permuted gate cols [c*128, c*128+128). W_hh slice resident in SMEM.
// h exchange: after activations each CTA pushes its 16x32 h slice into the
// double-buffered sA of all 16 cluster CTAs via st.shared::cluster, then one
// barrier.cluster per step. No L2 traffic, no flag protocol.
// smem halves: sW[128*520] | sA0[16*520] | sA1[16*520] | sG f32[16*132] | sH[16*32]
constexpr int LSTM_SMEM = 160 * 520 * 2 + 16 * 132 * 4 + 16 * 32 * 2;  // 175872 B

template <int LAYER>
__global__ __launch_bounds__(256, 1) __cluster_dims__(NSLICE, 1, 1) void k_lstm() {
    extern __shared__ __half smem[];
    __half* sW  = smem;                                  // [128][520]
    __half* sA0 = smem + 128 * 520;                      // [16][520]
    float*  sG  = (float*)(smem + 160 * 520);            // [16][132]
    __half* sH  = (__half*)(sG + 16 * 132);              // [16][32]

    const __half* __restrict__ Whh = LAYER ? g_whh1p : g_whh0p;

    int tid = threadIdx.x;
    int lane = tid & 31, warp = tid >> 5;
    int grp = blockIdx.x >> 4;
    int c = blockIdx.x & 15;       // == cluster rank
    int r = lane >> 2, tg = lane & 3;
    int jj = tid & 31;   // hidden-in-slice for activation phase
    int b2 = tid >> 5;   // row pair index (0..7)

    // load resident W slice: rows [c*128, c*128+128) of permuted W_hh
    {
        const uint4* src = (const uint4*)(Whh + (size_t)c * 128 * 512);
#pragma unroll
        for (int i = 0; i < 32; i++) {
            int u = tid + i * 256;
            int row = u >> 6, c4 = u & 63;
            ((uint4*)sW)[row * 65 + c4] = src[u];
        }
    }
    // zero both h buffers (h0 = 0)
    {
        uint4 z = make_uint4(0, 0, 0, 0);
        for (int i = tid; i < 2 * 16 * 520 / 8; i += 256) ((uint4*)sA0)[i] = z;
    }

    uint32_t sA_u = (uint32_t)__cvta_generic_to_shared(sA0);
    uint32_t sW_u = (uint32_t)__cvta_generic_to_shared(sW);
    const uint32_t bufB = 16 * 520 * 2;  // bytes per sA buffer
    uint32_t aBase[2] = { sA_u, sA_u + bufB };

    // ldmatrix lane bases
    uint32_t laneAoff = (uint32_t)((((lane & 15) * 520) + ((lane >> 4) << 3)) << 1);
    int bn = warp * 16 + ((lane >> 4) & 1) * 8 + (lane & 7);
    uint32_t bAddr = sW_u + (uint32_t)(((bn * 520) + ((lane >> 3) & 1) * 8) << 1);

    // DSMEM publish mapping: peer = tid>>4, row = tid&15, 4 x 16B chunks
    int peer = tid >> 4;
    int prow = tid & 15;

    float cs[2] = {0.f, 0.f};

    __syncthreads();
    asm volatile("barrier.cluster.arrive.aligned;" ::: "memory");
    asm volatile("barrier.cluster.wait.aligned;" ::: "memory");

    for (int t = 0; t < TT; t++) {
        // prefetch xg for this step (fp16, gates i,f,g,o interleaved per hidden unit)
        uint2 xgv[2];
#pragma unroll
        for (int q = 0; q < 2; q++) {
            int bgl = grp * BSUB + b2 * 2 + q;
            const __half* xp = g_xg + ((size_t)bgl * TT + t) * GG + c * 128 + jj * 4;
            xgv[q] = __ldcs((const uint2*)xp);
        }

        // GEMM: gates[16 x 128] = h_prev[16x512] @ Wslice^T ; warp owns 16 cols
        uint32_t aAddr = aBase[t & 1] + laneAoff;
        float acc[2][4] = {};
#pragma unroll 4
        for (int kt = 0; kt < 32; kt++) {
            uint32_t ko = (uint32_t)((kt * 16) << 1);
            uint32_t a[4];
            uint32_t p0, p1, p2, p3;
            ldsm4(a[0], a[1], a[2], a[3], aAddr + ko);
            ldsm4(p0, p1, p2, p3, bAddr + ko);
            mma16816(acc[0], a, p0, p1);
            mma16816(acc[1], a, p2, p3);
        }
        // scatter gates to smem (cross-warp exchange)
#pragma unroll
        for (int nt = 0; nt < 2; nt++) {
            int col = warp * 16 + nt * 8 + tg * 2;
            *(float2*)&sG[r * 132 + col]       = make_float2(acc[nt][0], acc[nt][1]);
            *(float2*)&sG[(r + 8) * 132 + col] = make_float2(acc[nt][2], acc[nt][3]);
        }
        __syncthreads();

        // activations: thread handles hidden jj for 2 batch rows, gates i,f,g,o packed
#pragma unroll
        for (int q = 0; q < 2; q++) {
            int b = b2 * 2 + q;
            float4 gv = *(float4*)&sG[b * 132 + jj * 4];
            __half2 x01 = *(__half2*)&xgv[q].x;   // i, f
            __half2 x23 = *(__half2*)&xgv[q].y;   // g, o
            float ip = gv.x + __low2float(x01);
            float fp = gv.y + __high2float(x01);
            float gp = gv.z + __low2float(x23);
            float op = gv.w + __high2float(x23);
            float ig = sigm(ip), fg = sigm(fp), gvv = tanhfast(gp), og = sigm(op);
            float cv = fg * cs[q] + ig * gvv;
            cs[q] = cv;
            float hv = og * tanhfast(cv);
            sH[b * 32 + jj] = __float2half(hv);
        }
        __syncthreads();

        // DSMEM publish: push my 16x32 h slice into every cluster CTA's next sA buffer
        {
            uint32_t localAddr = aBase[(t + 1) & 1]
                               + (uint32_t)((prow * 520 + c * 32) << 1);
            uint32_t rA;
            asm("mapa.shared::cluster.u32 %0, %1, %2;" : "=r"(rA) : "r"(localAddr), "r"(peer));
#pragma unroll
            for (int j = 0; j < 4; j++) {
                uint4 v = *(uint4*)&sH[prow * 32 + j * 8];
                asm volatile("st.shared::cluster.v2.b32 [%0], {%1,%2};"
                             :: "r"(rA + j * 16), "r"(v.x), "r"(v.y) : "memory");
                asm volatile("st.shared::cluster.v2.b32 [%0], {%1,%2};"
                             :: "r"(rA + j * 16 + 8), "r"(v.z), "r"(v.w) : "memory");
            }
        }
        // off-critical-path global writes
        if (LAYER == 0 && tid < 64) {
            int row16 = tid >> 2, chunk = tid & 3;
            uint4 hv4 = *(uint4*)&sH[row16 * 32 + chunk * 8];
            int bgl = grp * BSUB + row16;
            *(uint4*)&g_h1[((size_t)bgl * TT + t) * HH + c * 32 + chunk * 8] = hv4;
        }
        if (LAYER == 1 && t == TT - 1 && tid < 64) {
            int row16 = tid >> 2, chunk = tid & 3;
            int bgl = grp * BSUB + row16;
            const __half* hp = &sH[row16 * 32 + chunk * 8];
            float* dp = &g_hlast[bgl * HH + c * 32 + chunk * 8];
#pragma unroll
            for (int e = 0; e < 8; e++) dp[e] = __half2float(hp[e]);
        }

        asm volatile("barrier.cluster.arrive.aligned;" ::: "memory");
        asm volatile("barrier.cluster.wait.aligned;" ::: "memory");
    }
}

// ---------------- final FC + sigmoid ----------------
__global__ void k_fc(const float* __restrict__ wfc, const float* __restrict__ bfc,
                     float* __restrict__ out) {
    int w = blockIdx.x * 4 + (threadIdx.x >> 5);
    int lane = threadIdx.x & 31;
    if (w < BB) {
        float s = 0.f;
        for (int k = lane; k < HH; k += 32) s += g_hlast[w * HH + k] * wfc[k];
#pragma unroll
        for (int o = 16; o; o >>= 1) s += __shfl_xor_sync(0xffffffffu, s, o);
        if (lane == 0) out[w] = 1.f / (1.f + __expf(-(s + bfc[0])));
    }
}

// ---------------- launch ----------------
extern "C" void kernel_launch(void* const* d_in, const int* in_sizes, int n_in,
                              void* d_out, int out_size) {
    const float* x    = (const float*)d_in[0];
    const float* wih0 = (const float*)d_in[1];
    const float* whh0 = (const float*)d_in[2];
    const float* bih0 = (const float*)d_in[3];
    const float* bhh0 = (const float*)d_in[4];
    const float* wih1 = (const float*)d_in[5];
    const float* whh1 = (const float*)d_in[6];
    const float* bih1 = (const float*)d_in[7];
    const float* bhh1 = (const float*)d_in[8];
    const float* wfc  = (const float*)d_in[9];
    const float* bfc  = (const float*)d_in[10];
    float* out = (float*)d_out;

    cudaFuncSetAttribute(k_lstm<0>, cudaFuncAttributeMaxDynamicSharedMemorySize, LSTM_SMEM);
    cudaFuncSetAttribute(k_lstm<1>, cudaFuncAttributeMaxDynamicSharedMemorySize, LSTM_SMEM);
    cudaFuncSetAttribute(k_lstm<0>, cudaFuncAttributeNonPortableClusterSizeAllowed, 1);
    cudaFuncSetAttribute(k_lstm<1>, cudaFuncAttributeNonPortableClusterSizeAllowed, 1);
    cudaFuncSetAttribute(k_gemm_xg<EE>, cudaFuncAttributeMaxDynamicSharedMemorySize, GEMM_SMEM);
    cudaFuncSetAttribute(k_gemm_xg<HH>, cudaFuncAttributeMaxDynamicSharedMemorySize, GEMM_SMEM);

    // prep: fp16 conversions + gate-column permutation
    k_conv_x<<<(MR * EE + 255) / 256, 256>>>(x);
    k_prep_w<<<dim3((GG * HH + 255) / 256, 4), 256>>>(wih0, whh0, wih1, whh1);
    k_prep_b<<<dim3((GG + 255) / 256, 2), 256>>>(bih0, bhh0, bih1, bhh1);

    // layer 1
    k_gemm_xg<EE><<<dim3(GG / 64, MR / 128), 256, GEMM_SMEM>>>(0);
    k_lstm<0><<<NGROUP * NSLICE, 256, LSTM_SMEM>>>();

    // layer 2
    k_gemm_xg<HH><<<dim3(GG / 64, MR / 128), 256, GEMM_SMEM>>>(1);
    k_lstm<1><<<NGROUP * NSLICE, 256, LSTM_SMEM>>>();

    // head
    k_fc<<<(BB + 3) / 4, 128>>>(wfc, bfc, out);
}

// round 6
// speedup vs baseline: 2.2004x; 2.2004x over previous
#include <cuda_runtime.h>
#include <cuda_fp16.h>
#include <stdint.h>

// Problem constants
constexpr int BB = 128;    // batch
constexpr int TT = 512;    // seq len
constexpr int EE = 256;    // embed
constexpr int HH = 512;    // hidden
constexpr int GG = 2048;   // 4*H gates
constexpr int MR = BB * TT;  // 65536 rows

constexpr int NGROUP = 8;   // batch groups
constexpr int NSLICE = 16;  // CTAs per group
constexpr int BSUB   = 16;  // batch rows per group

// ---------------- static device scratch (allocation-free) ----------------
__device__ __half g_x16[(size_t)MR * EE];
__device__ __half g_h1 [(size_t)MR * HH];
__device__ __half g_xg [(size_t)MR * GG];     // 256 MB fp16, reused across layers
__device__ __half g_wih0p[GG * EE];
__device__ __half g_wih1p[GG * HH];
__device__ __half g_whh0p[GG * HH];
__device__ __half g_whh1p[GG * HH];
__device__ float  g_bias0[GG];
__device__ float  g_bias1[GG];
__device__ __half g_hbuf[2 * BB * HH];        // double-buffered h exchange
__device__ float  g_hlast[BB * HH];
__device__ int    g_flag[NGROUP * NSLICE * 32]; // 128B-spread barrier flags

// Column permutation: new index m -> original gate column n
// m = c*128 + u*4 + q  (c = CTA slice 0..15, u = hidden-in-slice 0..31, q = gate 0..3)
// n = q*512 + c*32 + u   (gates interleaved per hidden unit -> uint2 xg loads)
__device__ __forceinline__ int perm_orig(int m) {
    int cc = m >> 7, l = m & 127, u = l >> 2, q = l & 3;
    return q * 512 + cc * 32 + u;
}

// ---------------- prep kernels ----------------
__global__ void k_conv_x(const float* __restrict__ x) {
    size_t i = (size_t)blockIdx.x * blockDim.x + threadIdx.x;
    if (i < (size_t)MR * EE) g_x16[i] = __float2half(x[i]);
}

__global__ void k_prep_w(const float* __restrict__ wih0, const float* __restrict__ whh0,
                         const float* __restrict__ wih1, const float* __restrict__ whh1) {
    int which = blockIdx.y;
    size_t i = (size_t)blockIdx.x * blockDim.x + threadIdx.x;
    const float* src; __half* dst; int K;
    if      (which == 0) { src = wih0; dst = g_wih0p; K = EE; }
    else if (which == 1) { src = whh0; dst = g_whh0p; K = HH; }
    else if (which == 2) { src = wih1; dst = g_wih1p; K = HH; }
    else                 { src = whh1; dst = g_whh1p; K = HH; }
    if (i >= (size_t)GG * K) return;
    int m = (int)(i / K), k = (int)(i % K);
    int n = perm_orig(m);
    dst[i] = __float2half(src[(size_t)n * K + k]);
}

__global__ void k_prep_b(const float* __restrict__ bih0, const float* __restrict__ bhh0,
                         const float* __restrict__ bih1, const float* __restrict__ bhh1) {
    int m = blockIdx.x * blockDim.x + threadIdx.x;
    if (m >= GG) return;
    int n = perm_orig(m);
    if (blockIdx.y == 0) g_bias0[m] = bih0[n] + bhh0[n];
    else                 g_bias1[m] = bih1[n] + bhh1[n];
}

__global__ void k_reset() {
    int i = blockIdx.x * blockDim.x + threadIdx.x;
    if (i < 2 * BB * HH / 2) ((uint32_t*)g_hbuf)[i] = 0u;
    if (i < NGROUP * NSLICE * 32) g_flag[i] = 0;
}

// ---------------- asm helpers ----------------
__device__ __forceinline__ void mma16816(float* d, const uint32_t* a, uint32_t b0, uint32_t b1) {
    asm volatile(
        "mma.sync.aligned.m16n8k16.row.col.f32.f16.f16.f32 "
        "{%0,%1,%2,%3},{%4,%5,%6,%7},{%8,%9},{%0,%1,%2,%3};"
        : "+f"(d[0]), "+f"(d[1]), "+f"(d[2]), "+f"(d[3])
        : "r"(a[0]), "r"(a[1]), "r"(a[2]), "r"(a[3]), "r"(b0), "r"(b1));
}

__device__ __forceinline__ void ldsm4(uint32_t& r0, uint32_t& r1, uint32_t& r2, uint32_t& r3,
                                      uint32_t addr) {
    asm volatile("ldmatrix.sync.aligned.m8n8.x4.shared.b16 {%0,%1,%2,%3}, [%4];"
                 : "=r"(r0), "=r"(r1), "=r"(r2), "=r"(r3) : "r"(addr));
}

__device__ __forceinline__ void cp16(uint32_t dst, const void* src) {
    asm volatile("cp.async.cg.shared.global [%0], [%1], 16;" :: "r"(dst), "l"(src));
}
__device__ __forceinline__ void cp_commit() { asm volatile("cp.async.commit_group;"); }

__device__ __forceinline__ float tanhfast(float x) {
    float y;
    asm("tanh.approx.f32 %0, %1;" : "=f"(y) : "f"(x));
    return y;
}
__device__ __forceinline__ float sigm(float x) {
    return fmaf(0.5f, tanhfast(0.5f * x), 0.5f);
}

// ---------------- xg GEMM: C[M, 2048] = A[M,K] @ Wp^T + bias (fp16 out) ----------------
// BM=128, BN=64, BK=32, 256 threads (8 warps: 4 M x 2 N, warp tile 32x32)
// 5-stage cp.async ring (4 tiles in flight, tail-correct waits), 2 CTAs/SM.
constexpr int GEMM_STAGE = (128 + 64) * 40;            // halves per stage
constexpr int GEMM_SMEM  = 5 * GEMM_STAGE * 2;         // 76800 B

template <int K>
__global__ __launch_bounds__(256, 2) void k_gemm_xg(int layer) {
    const __half* __restrict__ A = layer ? g_h1    : g_x16;
    const __half* __restrict__ W = layer ? g_wih1p : g_wih0p;
    const float*  __restrict__ bias = layer ? g_bias1 : g_bias0;

    extern __shared__ __align__(16) __half gsm[];

    int tid = threadIdx.x;
    int m0 = blockIdx.y * 128;
    int n0 = blockIdx.x * 64;
    int lane = tid & 31, warp = tid >> 5;
    int wm = warp & 3, wn = warp >> 2;
    int r = lane >> 2, tg = lane & 3;

    uint32_t gsmu = (uint32_t)__cvta_generic_to_shared(gsm);
    const uint32_t stageB = GEMM_STAGE * 2;

    // cp.async indices: A 128x32 (2 uint4-chunks/thread), B 64x32 (1 chunk/thread)
    int ar0 = tid >> 2, ac4 = tid & 3;
    int br0 = tid >> 2, bc4 = tid & 3;

    // ldmatrix lane offsets (bytes), row stride 40 halves = 80 B
    uint32_t laneA = (uint32_t)(((lane & 15) * 40 + ((lane >> 4) << 3)) << 1);
    int bnn = wn * 32 + ((lane >> 4) & 1) * 8 + (lane & 7);
    uint32_t laneB = (uint32_t)((bnn * 40 + ((lane >> 3) & 1) * 8) << 1);

    float acc[2][4][4] = {};
    constexpr int KT = K / 32;

    auto load_stage = [&](int st, int kt) {
        uint32_t base = gsmu + st * stageB;
#pragma unroll
        for (int i = 0; i < 2; i++) {
            int row = ar0 + i * 64;
            cp16(base + (uint32_t)((row * 5 + ac4) * 16),
                 A + (size_t)(m0 + row) * K + kt * 32 + ac4 * 8);
        }
        cp16(base + (uint32_t)(128 * 80) + (uint32_t)((br0 * 5 + bc4) * 16),
             W + (size_t)(n0 + br0) * K + kt * 32 + bc4 * 8);
        cp_commit();
    };

#pragma unroll
    for (int s = 0; s < 4; s++)
        if (s < KT) load_stage(s, s);

    int st = 0;
#pragma unroll 1
    for (int kt = 0; kt < KT; kt++) {
        // tail-correct wait: group kt must be complete before consuming stage st
        int rem = KT - 1 - kt;
        if (rem >= 3)      asm volatile("cp.async.wait_group 3;");
        else if (rem == 2) asm volatile("cp.async.wait_group 2;");
        else if (rem == 1) asm volatile("cp.async.wait_group 1;");
        else               asm volatile("cp.async.wait_group 0;");
        __syncthreads();
        if (kt + 4 < KT) {
            int ns = st + 4; if (ns >= 5) ns -= 5;
            load_stage(ns, kt + 4);
        }
        uint32_t abase = gsmu + st * stageB;
        uint32_t bbase = abase + (uint32_t)(128 * 80);
#pragma unroll
        for (int kk = 0; kk < 2; kk++) {
            uint32_t kko = (uint32_t)(kk * 32);
            uint32_t a[2][4];
#pragma unroll
            for (int mt = 0; mt < 2; mt++) {
                uint32_t addr = abase + (uint32_t)(((wm * 32 + mt * 16) * 40) << 1) + laneA + kko;
                ldsm4(a[mt][0], a[mt][1], a[mt][2], a[mt][3], addr);
            }
            uint32_t p0, p1, p2, p3, q0, q1, q2, q3;
            ldsm4(p0, p1, p2, p3, bbase + laneB + kko);
            ldsm4(q0, q1, q2, q3, bbase + laneB + (uint32_t)((16 * 40) << 1) + kko);
#pragma unroll
            for (int mt = 0; mt < 2; mt++) {
                mma16816(acc[mt][0], a[mt], p0, p1);
                mma16816(acc[mt][1], a[mt], p2, p3);
                mma16816(acc[mt][2], a[mt], q0, q1);
                mma16816(acc[mt][3], a[mt], q2, q3);
            }
        }
        if (++st == 5) st = 0;
    }

    // epilogue: add bias, store fp16
#pragma unroll
    for (int mt = 0; mt < 2; mt++)
#pragma unroll
        for (int nt = 0; nt < 4; nt++) {
            int m = m0 + wm * 32 + mt * 16 + r;
            int n = n0 + wn * 32 + nt * 8 + tg * 2;
            float b0 = bias[n], b1 = bias[n + 1];
            __half2 v0 = __floats2half2_rn(acc[mt][nt][0] + b0, acc[mt][nt][1] + b1);
            __half2 v1 = __floats2half2_rn(acc[mt][nt][2] + b0, acc[mt][nt][3] + b1);
            *(__half2*)&g_xg[(size_t)m * GG + n] = v0;
            *(__half2*)&g_xg[(size_t)(m + 8) * GG + n] = v1;
        }
}

// ---------------- persistent LSTM recurrence ----------------
// 128 CTAs = 8 groups x 16 slices, 256 threads each (8 warps, 16 gate cols/warp).
// CTA (g,c): batch rows [g*16, g*16+16), hidden [c*32, c*32+32),
// permuted gate cols [c*128, c*128+128). W_hh slice resident in SMEM.
// h exchange via L2 (double-buffered g_hbuf) + release/acquire flag barrier.
constexpr int LSTM_SMEM = (128 * 520 + 16 * 520) * 2 + 16 * 132 * 4 + 16 * 32 * 2; // 159232 B

template <int LAYER>
__global__ __launch_bounds__(256, 1) void k_lstm() {
    extern __shared__ __half smem[];
    __half* sW = smem;                                   // [128][520]
    __half* sA = smem + 128 * 520;                       // [16][520]
    float*  sG = (float*)(smem + 144 * 520);             // [16][132]
    __half* sH = (__half*)(sG + 16 * 132);               // [16][32]

    const __half* __restrict__ Whh = LAYER ? g_whh1p : g_whh0p;

    int tid = threadIdx.x;
    int lane = tid & 31, warp = tid >> 5;
    int grp = blockIdx.x >> 4;
    int c = blockIdx.x & 15;
    int r = lane >> 2, tg = lane & 3;
    int jj = tid & 31;   // hidden-in-slice for activation phase
    int b2 = tid >> 5;   // row pair index (0..7)

    // load resident W slice: rows [c*128, c*128+128) of permuted W_hh
    {
        const uint4* src = (const uint4*)(Whh + (size_t)c * 128 * 512);
#pragma unroll
        for (int i = 0; i < 32; i++) {
            int u = tid + i * 256;
            int row = u >> 6, c4 = u & 63;
            ((uint4*)sW)[row * 65 + c4] = src[u];
        }
    }

    // ldmatrix lane bases
    uint32_t sA_u = (uint32_t)__cvta_generic_to_shared(sA);
    uint32_t sW_u = (uint32_t)__cvta_generic_to_shared(sW);
    uint32_t aAddr = sA_u + (uint32_t)((((lane & 15) * 520) + ((lane >> 4) << 3)) << 1);
    int bn = warp * 16 + ((lane >> 4) & 1) * 8 + (lane & 7);
    uint32_t bAddr = sW_u + (uint32_t)(((bn * 520) + ((lane >> 3) & 1) * 8) << 1);

    float cs[2] = {0.f, 0.f};
    int* myflag = &g_flag[(grp * NSLICE + c) * 32];
    int* pollflag = (tid >= 64 && tid < 80) ? &g_flag[(grp * NSLICE + (tid - 64)) * 32] : myflag;

    for (int t = 0; t < TT; t++) {
        // prefetch xg for this step (fp16, gates i,f,g,o interleaved per hidden unit)
        uint2 xgv[2];
#pragma unroll
        for (int q = 0; q < 2; q++) {
            int bgl = grp * BSUB + b2 * 2 + q;
            const __half* xp = g_xg + ((size_t)bgl * TT + t) * GG + c * 128 + jj * 4;
            xgv[q] = __ldcs((const uint2*)xp);
        }

        // load h_prev [16 x 512] fp16 from exchange buffer (L1-bypass: peers wrote it)
        {
            const uint4* src = (const uint4*)(g_hbuf + ((size_t)((t & 1) * BB + grp * BSUB)) * HH);
#pragma unroll
            for (int i = 0; i < 4; i++) {
                int u = tid + i * 256;
                int row = u >> 6, c4 = u & 63;
                ((uint4*)sA)[row * 65 + c4] = __ldcv(src + u);
            }
        }
        __syncthreads();

        // GEMM: gates[16 x 128] = h_prev[16x512] @ Wslice^T ; warp owns 16 cols
        float acc[2][4] = {};
#pragma unroll 4
        for (int kt = 0; kt < 32; kt++) {
            uint32_t ko = (uint32_t)((kt * 16) << 1);
            uint32_t a[4];
            uint32_t p0, p1, p2, p3;
            ldsm4(a[0], a[1], a[2], a[3], aAddr + ko);
            ldsm4(p0, p1, p2, p3, bAddr + ko);
            mma16816(acc[0], a, p0, p1);
            mma16816(acc[1], a, p2, p3);
        }
        // scatter gates to smem (cross-warp exchange)
#pragma unroll
        for (int nt = 0; nt < 2; nt++) {
            int col = warp * 16 + nt * 8 + tg * 2;
            *(float2*)&sG[r * 132 + col]       = make_float2(acc[nt][0], acc[nt][1]);
            *(float2*)&sG[(r + 8) * 132 + col] = make_float2(acc[nt][2], acc[nt][3]);
        }
        __syncthreads();

        // activations: thread handles hidden jj for 2 batch rows, gates i,f,g,o packed
#pragma unroll
        for (int q = 0; q < 2; q++) {
            int b = b2 * 2 + q;
            float4 gv = *(float4*)&sG[b * 132 + jj * 4];
            __half2 x01 = *(__half2*)&xgv[q].x;   // i, f
            __half2 x23 = *(__half2*)&xgv[q].y;   // g, o
            float ip = gv.x + __low2float(x01);
            float fp = gv.y + __high2float(x01);
            float gp = gv.z + __low2float(x23);
            float op = gv.w + __high2float(x23);
            float ig = sigm(ip), fg = sigm(fp), gvv = tanhfast(gp), og = sigm(op);
            float cv = fg * cs[q] + ig * gvv;
            cs[q] = cv;
            float hv = og * tanhfast(cv);
            sH[b * 32 + jj] = __float2half(hv);
        }
        __syncthreads();

        // publish h (64 writer threads, vectorized) + release; pollers overlap.
        // Only the g_hbuf store is release-ordered; g_h1/g_hlast go AFTER the
        // release (consumed only by later kernel launches).
        if (tid < 64) {
            int row16 = tid >> 2, chunk = tid & 3;
            uint4 hv4 = *(uint4*)&sH[row16 * 32 + chunk * 8];
            int bgl = grp * BSUB + row16;
            *(uint4*)&g_hbuf[((size_t)(((t + 1) & 1) * BB + bgl)) * HH + c * 32 + chunk * 8] = hv4;
            asm volatile("bar.sync 1, 64;");
            if (tid == 0)
                asm volatile("st.release.gpu.global.s32 [%0], %1;"
                             :: "l"(myflag), "r"(t + 1) : "memory");
            if (LAYER == 0)
                __stcs((uint4*)&g_h1[((size_t)bgl * TT + t) * HH + c * 32 + chunk * 8], hv4);
            if (LAYER == 1 && t == TT - 1) {
                const __half* hp = &sH[row16 * 32 + chunk * 8];
                float* dp = &g_hlast[bgl * HH + c * 32 + chunk * 8];
#pragma unroll
                for (int e = 0; e < 8; e++) dp[e] = __half2float(hp[e]);
            }
        } else if (tid < 80) {
            int v;
            do {
                asm volatile("ld.acquire.gpu.global.s32 %0, [%1];"
                             : "=r"(v) : "l"(pollflag) : "memory");
            } while (v <= t);
        }
        __syncthreads();
    }
}

// ---------------- final FC + sigmoid ----------------
__global__ void k_fc(const float* __restrict__ wfc, const float* __restrict__ bfc,
                     float* __restrict__ out) {
    int w = blockIdx.x * 4 + (threadIdx.x >> 5);
    int lane = threadIdx.x & 31;
    if (w < BB) {
        float s = 0.f;
        for (int k = lane; k < HH; k += 32) s += g_hlast[w * HH + k] * wfc[k];
#pragma unroll
        for (int o = 16; o; o >>= 1) s += __shfl_xor_sync(0xffffffffu, s, o);
        if (lane == 0) out[w] = 1.f / (1.f + __expf(-(s + bfc[0])));
    }
}

// ---------------- launch ----------------
extern "C" void kernel_launch(void* const* d_in, const int* in_sizes, int n_in,
                              void* d_out, int out_size) {
    const float* x    = (const float*)d_in[0];
    const float* wih0 = (const float*)d_in[1];
    const float* whh0 = (const float*)d_in[2];
    const float* bih0 = (const float*)d_in[3];
    const float* bhh0 = (const float*)d_in[4];
    const float* wih1 = (const float*)d_in[5];
    const float* whh1 = (const float*)d_in[6];
    const float* bih1 = (const float*)d_in[7];
    const float* bhh1 = (const float*)d_in[8];
    const float* wfc  = (const float*)d_in[9];
    const float* bfc  = (const float*)d_in[10];
    float* out = (float*)d_out;

    cudaFuncSetAttribute(k_lstm<0>, cudaFuncAttributeMaxDynamicSharedMemorySize, LSTM_SMEM);
    cudaFuncSetAttribute(k_lstm<1>, cudaFuncAttributeMaxDynamicSharedMemorySize, LSTM_SMEM);
    cudaFuncSetAttribute(k_gemm_xg<EE>, cudaFuncAttributeMaxDynamicSharedMemorySize, GEMM_SMEM);
    cudaFuncSetAttribute(k_gemm_xg<HH>, cudaFuncAttributeMaxDynamicSharedMemorySize, GEMM_SMEM);

    // prep: fp16 conversions + gate-column permutation
    k_conv_x<<<(MR * EE + 255) / 256, 256>>>(x);
    k_prep_w<<<dim3((GG * HH + 255) / 256, 4), 256>>>(wih0, whh0, wih1, whh1);
    k_prep_b<<<dim3((GG + 255) / 256, 2), 256>>>(bih0, bhh0, bih1, bhh1);

    // layer 1
    k_gemm_xg<EE><<<dim3(GG / 64, MR / 128), 256, GEMM_SMEM>>>(0);
    k_reset<<<256, 256>>>();
    k_lstm<0><<<NGROUP * NSLICE, 256, LSTM_SMEM>>>();

    // layer 2
    k_gemm_xg<HH><<<dim3(GG / 64, MR / 128), 256, GEMM_SMEM>>>(1);
    k_reset<<<256, 256>>>();
    k_lstm<1><<<NGROUP * NSLICE, 256, LSTM_SMEM>>>();

    // head
    k_fc<<<(BB + 3) / 4, 128>>>(wfc, bfc, out);
}

// round 7
// speedup vs baseline: 2.5863x; 1.1754x over previous
#include <cuda_runtime.h>
#include <cuda_fp16.h>
#include <stdint.h>

// Problem constants
constexpr int BB = 128;    // batch
constexpr int TT = 512;    // seq len
constexpr int EE = 256;    // embed
constexpr int HH = 512;    // hidden
constexpr int GG = 2048;   // 4*H gates
constexpr int MR = BB * TT;  // 65536 rows

constexpr int NGROUP = 8;   // batch groups
constexpr int NSLICE = 16;  // CTAs per group
constexpr int BSUB   = 16;  // batch rows per group

// ---------------- static device scratch (allocation-free) ----------------
__device__ __half g_x16[(size_t)MR * EE];
__device__ __half g_h1 [(size_t)MR * HH];
__device__ __half g_xg [(size_t)MR * GG];     // 256 MB fp16, reused across layers
__device__ __half g_wih0p[GG * EE];
__device__ __half g_wih1p[GG * HH];
__device__ __half g_whh0p[GG * HH];
__device__ __half g_whh1p[GG * HH];
__device__ float  g_bias0[GG];
__device__ float  g_bias1[GG];
// h exchange, per-peer contiguous: [parity][group][peer][row16][32 halves]
__device__ __half g_hbuf[2 * NGROUP * NSLICE * BSUB * 32];
__device__ float  g_hlast[BB * HH];
__device__ int    g_flag[NGROUP * NSLICE * 32]; // 128B-spread barrier flags

// Column permutation: new index m -> original gate column n
// m = c*128 + u*4 + q  (c = CTA slice 0..15, u = hidden-in-slice 0..31, q = gate 0..3)
// n = q*512 + c*32 + u   (gates interleaved per hidden unit -> uint2 xg loads)
__device__ __forceinline__ int perm_orig(int m) {
    int cc = m >> 7, l = m & 127, u = l >> 2, q = l & 3;
    return q * 512 + cc * 32 + u;
}

// ---------------- prep kernels ----------------
__global__ void k_conv_x(const float* __restrict__ x) {
    size_t i = (size_t)blockIdx.x * blockDim.x + threadIdx.x;
    if (i < (size_t)MR * EE) g_x16[i] = __float2half(x[i]);
}

__global__ void k_prep_w(const float* __restrict__ wih0, const float* __restrict__ whh0,
                         const float* __restrict__ wih1, const float* __restrict__ whh1) {
    int which = blockIdx.y;
    size_t i = (size_t)blockIdx.x * blockDim.x + threadIdx.x;
    const float* src; __half* dst; int K;
    if      (which == 0) { src = wih0; dst = g_wih0p; K = EE; }
    else if (which == 1) { src = whh0; dst = g_whh0p; K = HH; }
    else if (which == 2) { src = wih1; dst = g_wih1p; K = HH; }
    else                 { src = whh1; dst = g_whh1p; K = HH; }
    if (i >= (size_t)GG * K) return;
    int m = (int)(i / K), k = (int)(i % K);
    int n = perm_orig(m);
    dst[i] = __float2half(src[(size_t)n * K + k]);
}

__global__ void k_prep_b(const float* __restrict__ bih0, const float* __restrict__ bhh0,
                         const float* __restrict__ bih1, const float* __restrict__ bhh1) {
    int m = blockIdx.x * blockDim.x + threadIdx.x;
    if (m >= GG) return;
    int n = perm_orig(m);
    if (blockIdx.y == 0) g_bias0[m] = bih0[n] + bhh0[n];
    else                 g_bias1[m] = bih1[n] + bhh1[n];
}

__global__ void k_reset() {
    int i = blockIdx.x * blockDim.x + threadIdx.x;
    if (i < 2 * BB * HH / 2) ((uint32_t*)g_hbuf)[i] = 0u;
    if (i < NGROUP * NSLICE * 32) g_flag[i] = 0;
}

// ---------------- asm helpers ----------------
__device__ __forceinline__ void mma16816(float* d, const uint32_t* a, uint32_t b0, uint32_t b1) {
    asm volatile(
        "mma.sync.aligned.m16n8k16.row.col.f32.f16.f16.f32 "
        "{%0,%1,%2,%3},{%4,%5,%6,%7},{%8,%9},{%0,%1,%2,%3};"
        : "+f"(d[0]), "+f"(d[1]), "+f"(d[2]), "+f"(d[3])
        : "r"(a[0]), "r"(a[1]), "r"(a[2]), "r"(a[3]), "r"(b0), "r"(b1));
}

__device__ __forceinline__ void ldsm4(uint32_t& r0, uint32_t& r1, uint32_t& r2, uint32_t& r3,
                                      uint32_t addr) {
    asm volatile("ldmatrix.sync.aligned.m8n8.x4.shared.b16 {%0,%1,%2,%3}, [%4];"
                 : "=r"(r0), "=r"(r1), "=r"(r2), "=r"(r3) : "r"(addr));
}

__device__ __forceinline__ void cp16(uint32_t dst, const void* src) {
    asm volatile("cp.async.cg.shared.global [%0], [%1], 16;" :: "r"(dst), "l"(src));
}
__device__ __forceinline__ void cp_commit() { asm volatile("cp.async.commit_group;"); }

__device__ __forceinline__ float tanhfast(float x) {
    float y;
    asm("tanh.approx.f32 %0, %1;" : "=f"(y) : "f"(x));
    return y;
}
__device__ __forceinline__ float sigm(float x) {
    return fmaf(0.5f, tanhfast(0.5f * x), 0.5f);
}

// ---------------- xg GEMM: C[M, 2048] = A[M,K] @ Wp^T + bias (fp16 out) ----------------
// BM=128, BN=128, BK=32, 256 threads (8 warps: 4 M x 2 N, warp tile 32x64)
// 4-stage cp.async ring, loop-split tail waits (race-free), 2 CTAs/SM.
constexpr int GEMM_STAGE = (128 + 128) * 40;           // halves per stage
constexpr int GEMM_SMEM  = 4 * GEMM_STAGE * 2;         // 81920 B

template <int K>
__global__ __launch_bounds__(256, 2) void k_gemm_xg(int layer) {
    const __half* __restrict__ A = layer ? g_h1    : g_x16;
    const __half* __restrict__ W = layer ? g_wih1p : g_wih0p;
    const float*  __restrict__ bias = layer ? g_bias1 : g_bias0;

    extern __shared__ __align__(16) __half gsm[];

    int tid = threadIdx.x;
    int m0 = blockIdx.y * 128;
    int n0 = blockIdx.x * 128;
    int lane = tid & 31, warp = tid >> 5;
    int wm = warp & 3, wn = warp >> 2;
    int r = lane >> 2, tg = lane & 3;

    uint32_t gsmu = (uint32_t)__cvta_generic_to_shared(gsm);
    const uint32_t stageB = GEMM_STAGE * 2;

    // ldmatrix lane offsets (bytes), row stride 40 halves = 80 B
    uint32_t laneA = (uint32_t)(((lane & 15) * 40 + ((lane >> 4) << 3)) << 1);
    int bnn = wn * 64 + ((lane >> 4) & 1) * 8 + (lane & 7);
    uint32_t laneB = (uint32_t)((bnn * 40 + ((lane >> 3) & 1) * 8) << 1);

    float acc[2][8][4] = {};
    constexpr int KT = K / 32;

    auto load_stage = [&](int st, int kt) {
        uint32_t base = gsmu + st * stageB;
#pragma unroll
        for (int i = 0; i < 2; i++) {       // A: 128x32 -> 512 chunks / 256 thr
            int chunk = tid + i * 256;
            int row = chunk >> 2, c4 = chunk & 3;
            cp16(base + (uint32_t)((row * 40 + c4 * 8) * 2),
                 A + (size_t)(m0 + row) * K + kt * 32 + c4 * 8);
        }
#pragma unroll
        for (int i = 0; i < 2; i++) {       // B: 128x32
            int chunk = tid + i * 256;
            int row = chunk >> 2, c4 = chunk & 3;
            cp16(base + (uint32_t)(128 * 80) + (uint32_t)((row * 40 + c4 * 8) * 2),
                 W + (size_t)(n0 + row) * K + kt * 32 + c4 * 8);
        }
        cp_commit();
    };

    auto consume = [&](int st) {
        uint32_t abase = gsmu + st * stageB;
        uint32_t bbase = abase + (uint32_t)(128 * 80);
#pragma unroll
        for (int kk = 0; kk < 2; kk++) {
            uint32_t kko = (uint32_t)(kk * 32);
            uint32_t a[2][4];
#pragma unroll
            for (int mt = 0; mt < 2; mt++) {
                uint32_t addr = abase + (uint32_t)(((wm * 32 + mt * 16) * 40) << 1) + laneA + kko;
                ldsm4(a[mt][0], a[mt][1], a[mt][2], a[mt][3], addr);
            }
            uint32_t p[4][4];
#pragma unroll
            for (int q = 0; q < 4; q++)
                ldsm4(p[q][0], p[q][1], p[q][2], p[q][3],
                      bbase + laneB + (uint32_t)(q * 16 * 80) + kko);
#pragma unroll
            for (int mt = 0; mt < 2; mt++)
#pragma unroll
                for (int q = 0; q < 4; q++) {
                    mma16816(acc[mt][2 * q],     a[mt], p[q][0], p[q][1]);
                    mma16816(acc[mt][2 * q + 1], a[mt], p[q][2], p[q][3]);
                }
        }
    };

    load_stage(0, 0);
    load_stage(1, 1);
    load_stage(2, 2);

    int st = 0;
#pragma unroll 1
    for (int kt = 0; kt < KT - 3; kt++) {
        asm volatile("cp.async.wait_group 2;");
        __syncthreads();
        load_stage((st + 3) & 3, kt + 3);
        consume(st);
        st = (st + 1) & 3;
    }
    // tail: 3 iterations, no new issues
    asm volatile("cp.async.wait_group 2;");
    __syncthreads();
    consume(st); st = (st + 1) & 3;
    asm volatile("cp.async.wait_group 1;");
    __syncthreads();
    consume(st); st = (st + 1) & 3;
    asm volatile("cp.async.wait_group 0;");
    __syncthreads();
    consume(st);

    // epilogue: add bias, store fp16
#pragma unroll
    for (int mt = 0; mt < 2; mt++)
#pragma unroll
        for (int j = 0; j < 8; j++) {
            int m = m0 + wm * 32 + mt * 16 + r;
            int n = n0 + wn * 64 + (j >> 1) * 16 + (j & 1) * 8 + tg * 2;
            float b0 = bias[n], b1 = bias[n + 1];
            __half2 v0 = __floats2half2_rn(acc[mt][j][0] + b0, acc[mt][j][1] + b1);
            __half2 v1 = __floats2half2_rn(acc[mt][j][2] + b0, acc[mt][j][3] + b1);
            *(__half2*)&g_xg[(size_t)m * GG + n] = v0;
            *(__half2*)&g_xg[(size_t)(m + 8) * GG + n] = v1;
        }
}

// ---------------- persistent LSTM recurrence ----------------
// 128 CTAs = 8 groups x 16 slices, 256 threads (8 warps, 16 gate cols/warp).
// CTA (g,c): batch rows [g*16,g*16+16), hidden [c*32,c*32+32), permuted gate
// cols [c*128,c*128+128). W_hh fragments preloaded in REGISTERS (128/thread).
// h exchange per-peer contiguous in L2; warp w polls + copies peers 2w,2w+1.
constexpr int LSTM_SMEM = (128 * 520 + 16 * 520) * 2 + 16 * 132 * 4 + 16 * 32 * 2; // 159232 B

template <int LAYER>
__global__ __launch_bounds__(256, 1) void k_lstm() {
    extern __shared__ __half smem[];
    __half* sW = smem;                                   // [128][520] (init only)
    __half* sA = smem + 128 * 520;                       // [16][520]
    float*  sG = (float*)(smem + 144 * 520);             // [16][132]
    __half* sH = (__half*)(sG + 16 * 132);               // [16][32]

    const __half* __restrict__ Whh = LAYER ? g_whh1p : g_whh0p;

    int tid = threadIdx.x;
    int lane = tid & 31, warp = tid >> 5;
    int grp = blockIdx.x >> 4;
    int c = blockIdx.x & 15;
    int r = lane >> 2, tg = lane & 3;
    int jj = tid & 31;   // hidden-in-slice for activation phase
    int b2 = tid >> 5;   // row pair index (0..7)

    // load resident W slice rows [c*128, c*128+128) into smem (staging for frags)
    {
        const uint4* src = (const uint4*)(Whh + (size_t)c * 128 * 512);
#pragma unroll
        for (int i = 0; i < 32; i++) {
            int u = tid + i * 256;
            int row = u >> 6, c4 = u & 63;
            ((uint4*)sW)[row * 65 + c4] = src[u];
        }
    }
    __syncthreads();

    uint32_t sA_u = (uint32_t)__cvta_generic_to_shared(sA);
    uint32_t sW_u = (uint32_t)__cvta_generic_to_shared(sW);
    uint32_t aAddr = sA_u + (uint32_t)((((lane & 15) * 520) + ((lane >> 4) << 3)) << 1);

    // preload ALL W fragments into registers: warp owns 16 gate cols, full K=512
    uint32_t wf[32][4];
    {
        int bn = warp * 16 + ((lane >> 4) & 1) * 8 + (lane & 7);
        uint32_t bAddr = sW_u + (uint32_t)(((bn * 520) + ((lane >> 3) & 1) * 8) << 1);
#pragma unroll
        for (int kt = 0; kt < 32; kt++)
            ldsm4(wf[kt][0], wf[kt][1], wf[kt][2], wf[kt][3], bAddr + (uint32_t)(kt * 32));
    }

    float cs[2] = {0.f, 0.f};
    int* myflag = &g_flag[(grp * NSLICE + c) * 32];
    // warp w polls peers 2w, 2w+1
    int p0 = 2 * warp, p1 = 2 * warp + 1;
    int* f0 = &g_flag[(grp * NSLICE + p0) * 32];
    int* f1 = &g_flag[(grp * NSLICE + p1) * 32];

    for (int t = 0; t < TT; t++) {
        // prefetch xg for this step (fp16, gates i,f,g,o interleaved per hidden unit)
        uint2 xgv[2];
#pragma unroll
        for (int q = 0; q < 2; q++) {
            int bgl = grp * BSUB + b2 * 2 + q;
            const __half* xp = g_xg + ((size_t)bgl * TT + t) * GG + c * 128 + jj * 4;
            xgv[q] = __ldcs((const uint2*)xp);
        }

        // poll my 2 peers (flag >= t means they published h[t]); t=0 passes free
        if (t > 0) {
            int v0, v1;
            do {
                asm volatile("ld.acquire.gpu.global.s32 %0, [%1];" : "=r"(v0) : "l"(f0) : "memory");
                asm volatile("ld.acquire.gpu.global.s32 %0, [%1];" : "=r"(v1) : "l"(f1) : "memory");
            } while (v0 < t || v1 < t);
        }
        // copy their h chunks (1 KB each, per-peer contiguous) into sA
        {
            int par = t & 1;
            const uint4* s0 = (const uint4*)&g_hbuf[(((size_t)par * NGROUP + grp) * NSLICE + p0) * 512];
            const uint4* s1 = (const uint4*)&g_hbuf[(((size_t)par * NGROUP + grp) * NSLICE + p1) * 512];
#pragma unroll
            for (int j = 0; j < 2; j++) {
                int chunk = lane + j * 32;           // 64 x 16B = 1 KB
                int row = chunk >> 2, c4 = chunk & 3;
                *(uint4*)&sA[row * 520 + p0 * 32 + c4 * 8] = __ldcv(s0 + chunk);
                *(uint4*)&sA[row * 520 + p1 * 32 + c4 * 8] = __ldcv(s1 + chunk);
            }
        }
        __syncthreads();

        // GEMM: gates[16 x 128] = h_prev[16x512] @ Wslice^T ; warp owns 16 cols
        float acc[2][4] = {};
#pragma unroll
        for (int kt = 0; kt < 32; kt++) {
            uint32_t a[4];
            ldsm4(a[0], a[1], a[2], a[3], aAddr + (uint32_t)(kt * 32));
            mma16816(acc[0], a, wf[kt][0], wf[kt][1]);
            mma16816(acc[1], a, wf[kt][2], wf[kt][3]);
        }
        // scatter gates to smem (cross-warp exchange)
#pragma unroll
        for (int nt = 0; nt < 2; nt++) {
            int col = warp * 16 + nt * 8 + tg * 2;
            *(float2*)&sG[r * 132 + col]       = make_float2(acc[nt][0], acc[nt][1]);
            *(float2*)&sG[(r + 8) * 132 + col] = make_float2(acc[nt][2], acc[nt][3]);
        }
        __syncthreads();

        // activations: thread handles hidden jj for 2 batch rows, gates i,f,g,o packed
#pragma unroll
        for (int q = 0; q < 2; q++) {
            int b = b2 * 2 + q;
            float4 gv = *(float4*)&sG[b * 132 + jj * 4];
            __half2 x01 = *(__half2*)&xgv[q].x;   // i, f
            __half2 x23 = *(__half2*)&xgv[q].y;   // g, o
            float ip = gv.x + __low2float(x01);
            float fp = gv.y + __high2float(x01);
            float gp = gv.z + __low2float(x23);
            float op = gv.w + __high2float(x23);
            float ig = sigm(ip), fg = sigm(fp), gvv = tanhfast(gp), og = sigm(op);
            float cv = fg * cs[q] + ig * gvv;
            cs[q] = cv;
            float hv = og * tanhfast(cv);
            sH[b * 32 + jj] = __float2half(hv);
        }
        __syncthreads();

        // publish own 1 KB h chunk (64 writers) + release; other warps run ahead
        if (tid < 64) {
            int row = tid >> 2, c4 = tid & 3;
            uint4 hv4 = *(uint4*)&sH[row * 32 + c4 * 8];
            int par = (t + 1) & 1;
            *(uint4*)&g_hbuf[(((size_t)par * NGROUP + grp) * NSLICE + c) * 512
                             + row * 32 + c4 * 8] = hv4;
            asm volatile("bar.sync 1, 64;");
            if (tid == 0)
                asm volatile("st.release.gpu.global.s32 [%0], %1;"
                             :: "l"(myflag), "r"(t + 1) : "memory");
            int bgl = grp * BSUB + row;
            if (LAYER == 0)
                __stcs((uint4*)&g_h1[((size_t)bgl * TT + t) * HH + c * 32 + c4 * 8], hv4);
            if (LAYER == 1 && t == TT - 1) {
                const __half* hp = &sH[row * 32 + c4 * 8];
                float* dp = &g_hlast[bgl * HH + c * 32 + c4 * 8];
#pragma unroll
                for (int e = 0; e < 8; e++) dp[e] = __half2float(hp[e]);
            }
        }
        __syncthreads();
    }
}

// ---------------- final FC + sigmoid ----------------
__global__ void k_fc(const float* __restrict__ wfc, const float* __restrict__ bfc,
                     float* __restrict__ out) {
    int w = blockIdx.x * 4 + (threadIdx.x >> 5);
    int lane = threadIdx.x & 31;
    if (w < BB) {
        float s = 0.f;
        for (int k = lane; k < HH; k += 32) s += g_hlast[w * HH + k] * wfc[k];
#pragma unroll
        for (int o = 16; o; o >>= 1) s += __shfl_xor_sync(0xffffffffu, s, o);
        if (lane == 0) out[w] = 1.f / (1.f + __expf(-(s + bfc[0])));
    }
}

// ---------------- launch ----------------
extern "C" void kernel_launch(void* const* d_in, const int* in_sizes, int n_in,
                              void* d_out, int out_size) {
    const float* x    = (const float*)d_in[0];
    const float* wih0 = (const float*)d_in[1];
    const float* whh0 = (const float*)d_in[2];
    const float* bih0 = (const float*)d_in[3];
    const float* bhh0 = (const float*)d_in[4];
    const float* wih1 = (const float*)d_in[5];
    const float* whh1 = (const float*)d_in[6];
    const float* bih1 = (const float*)d_in[7];
    const float* bhh1 = (const float*)d_in[8];
    const float* wfc  = (const float*)d_in[9];
    const float* bfc  = (const float*)d_in[10];
    float* out = (float*)d_out;

    cudaFuncSetAttribute(k_lstm<0>, cudaFuncAttributeMaxDynamicSharedMemorySize, LSTM_SMEM);
    cudaFuncSetAttribute(k_lstm<1>, cudaFuncAttributeMaxDynamicSharedMemorySize, LSTM_SMEM);
    cudaFuncSetAttribute(k_gemm_xg<EE>, cudaFuncAttributeMaxDynamicSharedMemorySize, GEMM_SMEM);
    cudaFuncSetAttribute(k_gemm_xg<HH>, cudaFuncAttributeMaxDynamicSharedMemorySize, GEMM_SMEM);

    // prep: fp16 conversions + gate-column permutation
    k_conv_x<<<(MR * EE + 255) / 256, 256>>>(x);
    k_prep_w<<<dim3((GG * HH + 255) / 256, 4), 256>>>(wih0, whh0, wih1, whh1);
    k_prep_b<<<dim3((GG + 255) / 256, 2), 256>>>(bih0, bhh0, bih1, bhh1);

    // layer 1
    k_gemm_xg<EE><<<dim3(GG / 128, MR / 128), 256, GEMM_SMEM>>>(0);
    k_reset<<<256, 256>>>();
    k_lstm<0><<<NGROUP * NSLICE, 256, LSTM_SMEM>>>();

    // layer 2
    k_gemm_xg<HH><<<dim3(GG / 128, MR / 128), 256, GEMM_SMEM>>>(1);
    k_reset<<<256, 256>>>();
    k_lstm<1><<<NGROUP * NSLICE, 256, LSTM_SMEM>>>();

    // head
    k_fc<<<(BB + 3) / 4, 128>>>(wfc, bfc, out);
}